// round 1
// baseline (speedup 1.0000x reference)
#include <cuda_runtime.h>
#include <cstdint>

// Problem constants (fixed shapes per reference)
#define BN   4096          // batch
#define TT   100           // time steps
#define DD   784           // input dim
#define HH   10            // hidden/output units
#define MM   (BN * TT)     // GEMM rows = 409600
#define NBH  (BN * HH)     // 40960
#define ROWS 256           // rows per block in proj kernel
#define KC   32            // K-chunk
#define XS   36            // padded smem row stride (floats), 16B-aligned

#define ALPHA_F 0.8187307530779818f   // exp(-0.001/0.005)
#define BETA_F  0.9048374180359595f   // exp(-0.001/0.010)

// Scratch: proj[t][b][h], t-major so the scan kernel reads fully coalesced.
__device__ float g_proj[(size_t)TT * BN * HH];

// ---- packed f32x2 helpers (Blackwell) ----
__device__ __forceinline__ void fma2(unsigned long long& acc,
                                     unsigned long long a,
                                     unsigned long long b) {
    asm("fma.rn.f32x2 %0, %1, %2, %0;" : "+l"(acc) : "l"(a), "l"(b));
}
__device__ __forceinline__ void unpk(float& lo, float& hi, unsigned long long v) {
    asm("mov.b64 {%0,%1}, %2;" : "=f"(lo), "=f"(hi) : "l"(v));
}

// ============================================================================
// Kernel 1: proj[t,b,h] = dot(x[b,t,:], W[h,:]) + bias[h]
// Thread-per-row (m = b*TT + t). x chunk staged in smem (read once per elem),
// W chunk in smem read via broadcast LDS.128 (conflict-degree 1).
// ============================================================================
__global__ __launch_bounds__(ROWS) void proj_kernel(
    const float* __restrict__ x,
    const float* __restrict__ W,
    const float* __restrict__ bias)
{
    __shared__ float xs[ROWS * XS];   // 36864 B
    __shared__ float ws[HH * KC];     //  1280 B

    const int tid = threadIdx.x;
    const int m0  = blockIdx.x * ROWS;

    unsigned long long acc[HH];
#pragma unroll
    for (int h = 0; h < HH; h++) acc[h] = 0ull;  // packed (0.f, 0.f)

    // 25 chunks of 32 cover K=784 (last chunk half-valid, zero-padded)
    for (int c = 0; c < 25; c++) {
        const int kb = c * KC;
        __syncthreads();

        // Stage x[m0..m0+255, kb..kb+31]: 2048 float4, 8 per thread.
        // idx = j*256 + tid -> 8 consecutive threads cover one row's 128B chunk.
#pragma unroll
        for (int j = 0; j < 8; j++) {
            int idx = j * ROWS + tid;
            int row = idx >> 3;
            int c4  = idx & 7;
            int k   = kb + c4 * 4;
            float4 v = make_float4(0.f, 0.f, 0.f, 0.f);
            if (k < DD)
                v = *(const float4*)(x + (size_t)(m0 + row) * DD + k);
            *(float4*)&xs[row * XS + c4 * 4] = v;
        }
        // Stage W[0..9, kb..kb+31]: 80 float4 (L2-resident after first block)
        if (tid < 80) {
            int h  = tid >> 3;
            int c4 = tid & 7;
            int k  = kb + c4 * 4;
            float4 v = make_float4(0.f, 0.f, 0.f, 0.f);
            if (k < DD)
                v = *(const float4*)(W + h * DD + k);
            *(float4*)&ws[h * KC + c4 * 4] = v;
        }
        __syncthreads();

        // Compute: per float4 of x, 10 broadcast W float4s, 20 packed FMAs.
#pragma unroll
        for (int i = 0; i < 8; i++) {
            ulonglong2 xv = *(const ulonglong2*)&xs[tid * XS + i * 4];
#pragma unroll
            for (int h = 0; h < HH; h++) {
                ulonglong2 wv = *(const ulonglong2*)&ws[h * KC + i * 4];
                fma2(acc[h], xv.x, wv.x);
                fma2(acc[h], xv.y, wv.y);
            }
        }
    }

    // Epilogue: reduce pairs, add bias, scatter to t-major proj buffer.
    const int m  = m0 + tid;
    const int bb = m / TT;
    const int tt = m - bb * TT;
    float* outp = g_proj + (size_t)tt * NBH + bb * HH;
#pragma unroll
    for (int h = 0; h < HH; h++) {
        float lo, hi;
        unpk(lo, hi, acc[h]);
        outp[h] = lo + hi + __ldg(bias + h);
    }
}

// ============================================================================
// Kernel 2: LIF scan over T=100 steps, one thread per (b,h) lane.
// spk_rec at out[0 .. 101*NBH), mem_rec at out[101*NBH .. 2*101*NBH).
// Row 0 of both records is zeros (the initial state), matching reference.
// ============================================================================
__global__ __launch_bounds__(256) void scan_kernel(float* __restrict__ out)
{
    const int u = blockIdx.x * blockDim.x + threadIdx.x;  // 0..NBH-1
    const size_t MOFF = (size_t)(TT + 1) * NBH;

    float syn = 0.f, mem = 0.f;
    out[u] = 0.f;           // spk_rec[0]
    out[MOFF + u] = 0.f;    // mem_rec[0]

#pragma unroll 4
    for (int t = 0; t < TT; t++) {
        float inp   = g_proj[(size_t)t * NBH + u];
        float mthr  = mem - 1.0f;
        float spike = (mthr > 0.0f) ? 1.0f : 0.0f;
        float nsyn  = ALPHA_F * syn + inp;
        float nmem  = BETA_F * mem + syn - spike;   // uses OLD syn (as in ref)
        out[(size_t)(t + 1) * NBH + u]        = spike;
        out[MOFF + (size_t)(t + 1) * NBH + u] = nmem;
        syn = nsyn;
        mem = nmem;
    }
}

// ============================================================================
extern "C" void kernel_launch(void* const* d_in, const int* in_sizes, int n_in,
                              void* d_out, int out_size)
{
    const float* x    = (const float*)d_in[0];  // (4096, 100, 784)
    const float* W    = (const float*)d_in[1];  // (10, 784)
    const float* bias = (const float*)d_in[2];  // (10,)
    float* out = (float*)d_out;                 // 2 * 101 * 4096 * 10 floats

    proj_kernel<<<MM / ROWS, ROWS>>>(x, W, bias);
    scan_kernel<<<NBH / 256, 256>>>(out);
}

// round 2
// speedup vs baseline: 1.6682x; 1.6682x over previous
#include <cuda_runtime.h>
#include <cstdint>

// Problem constants
#define BN   4096
#define TT   100
#define DD   784
#define HH   10
#define MM   (BN * TT)        // 409600 rows
#define NBH  (BN * HH)        // 40960

// proj kernel config
#define BLK  256              // threads per block
#define RPB  512              // rows per block (2 rows/thread)
#define KC   32               // K-chunk (floats)
#define NCH  25               // chunks (25*32 = 800 >= 784, zero-padded)
#define WS_STRIDE 800         // padded W row stride (floats)
#define XS_ELEMS (RPB * KC)   // floats per x buffer

#define ALPHA_F 0.8187307530779818f   // exp(-0.001/0.005)
#define BETA_F  0.9048374180359595f   // exp(-0.001/0.010)

// Scratch: proj[t][b][h], t-major so scan reads fully coalesced.
__device__ float g_proj[(size_t)TT * BN * HH];

// ---- packed f32x2 FMA (Blackwell FFMA2) ----
__device__ __forceinline__ void fma2(unsigned long long& acc,
                                     unsigned long long a,
                                     unsigned long long b) {
    asm("fma.rn.f32x2 %0, %1, %2, %0;" : "+l"(acc) : "l"(a), "l"(b));
}
__device__ __forceinline__ void unpk(float& lo, float& hi, unsigned long long v) {
    asm("mov.b64 {%0,%1}, %2;" : "=f"(lo), "=f"(hi) : "l"(v));
}

// ---- cp.async helpers ----
__device__ __forceinline__ void cp16(uint32_t saddr, const void* gptr, int src_size) {
    asm volatile("cp.async.cg.shared.global [%0], [%1], 16, %2;"
                 :: "r"(saddr), "l"(gptr), "r"(src_size));
}
__device__ __forceinline__ void cp_commit() { asm volatile("cp.async.commit_group;"); }
__device__ __forceinline__ void cp_wait1()  { asm volatile("cp.async.wait_group 1;" ::: "memory"); }
__device__ __forceinline__ void cp_wait0()  { asm volatile("cp.async.wait_group 0;" ::: "memory"); }

// ============================================================================
// Kernel 1: proj[t,b,h] = dot(x[b,t,:], W[h,:]) + bias[h]
// 2 rows/thread, W resident in smem for the whole kernel, x double-buffered
// via cp.async, XOR-swizzled stride-32 smem rows (conflict-free LDS.128).
// ============================================================================
__global__ void __launch_bounds__(BLK, 1) proj_kernel(
    const float* __restrict__ x,
    const float* __restrict__ W,
    const float* __restrict__ bias)
{
    extern __shared__ float smem[];
    float* xs = smem;                   // [2][XS_ELEMS]
    float* ws = smem + 2 * XS_ELEMS;    // [HH][WS_STRIDE]

    const int tid = threadIdx.x;
    const int m0  = blockIdx.x * RPB;

    // ---- Stage W once: zero-fill (for K padding) then copy 10x784 ----
    for (int i = tid; i < HH * WS_STRIDE / 4; i += BLK)
        ((float4*)ws)[i] = make_float4(0.f, 0.f, 0.f, 0.f);
    __syncthreads();   // zeros visible before partial overwrite below reads? (write-only; barrier orders zero vs copy)
    for (int idx = tid; idx < HH * (DD / 4); idx += BLK) {
        int h = idx / (DD / 4);
        int q = idx - h * (DD / 4);
        ((float4*)(ws + h * WS_STRIDE))[q] = ((const float4*)(W + h * DD))[q];
    }

    // ---- x staging lambda: chunk c -> buffer (c&1), swizzled ----
    auto stage = [&](int c) {
        const int kb   = c * KC;
        const int bsel = c & 1;
        float* dst = xs + bsel * XS_ELEMS;
#pragma unroll
        for (int j = 0; j < 16; j++) {
            int idx = j * BLK + tid;       // 0..4095
            int row = idx >> 3;            // 0..511
            int c4  = idx & 7;             // 0..7
            int k   = kb + c4 * 4;
            int ok  = (k < DD) ? 16 : 0;
            const float* g = x + (size_t)(m0 + row) * DD + (ok ? k : 0);
            uint32_t s = (uint32_t)__cvta_generic_to_shared(
                dst + row * KC + ((c4 ^ (row & 7)) << 2));
            cp16(s, g, ok);
        }
    };

    // Prologue: chunk 0 in flight
    stage(0);
    cp_commit();

    unsigned long long a0[HH], a1[HH];
#pragma unroll
    for (int h = 0; h < HH; h++) { a0[h] = 0ull; a1[h] = 0ull; }

    const int r0 = tid;
    const int r1 = tid + BLK;
    const int sw = r0 & 7;      // same for r1 (256 % 8 == 0)

    for (int c = 0; c < NCH; c++) {
        __syncthreads();                 // everyone done reading buffer (c+1)&1
        if (c + 1 < NCH) {
            stage(c + 1);
            cp_commit();
            cp_wait1();                  // chunk c complete, c+1 in flight
        } else {
            cp_wait0();
        }
        __syncthreads();                 // chunk c visible to all threads

        const float* xb = xs + (c & 1) * XS_ELEMS;
        const int kb = c * KC;
#pragma unroll
        for (int i = 0; i < 8; i++) {
            ulonglong2 x0 = *(const ulonglong2*)&xb[r0 * KC + ((i ^ sw) << 2)];
            ulonglong2 x1 = *(const ulonglong2*)&xb[r1 * KC + ((i ^ sw) << 2)];
#pragma unroll
            for (int h = 0; h < HH; h++) {
                ulonglong2 wv = *(const ulonglong2*)&ws[h * WS_STRIDE + kb + i * 4];
                fma2(a0[h], x0.x, wv.x);
                fma2(a1[h], x1.x, wv.x);
                fma2(a0[h], x0.y, wv.y);
                fma2(a1[h], x1.y, wv.y);
            }
        }
    }

    // ---- Epilogue: reduce pairs, add bias, scatter to t-major proj ----
#pragma unroll
    for (int rr = 0; rr < 2; rr++) {
        int m  = m0 + tid + rr * BLK;
        int bb = m / TT;
        int tt = m - bb * TT;
        float* outp = g_proj + (size_t)tt * NBH + bb * HH;
        unsigned long long* acc = rr ? a1 : a0;
#pragma unroll
        for (int h = 0; h < HH; h++) {
            float lo, hi;
            unpk(lo, hi, acc[h]);
            outp[h] = lo + hi + __ldg(bias + h);
        }
    }
}

// ============================================================================
// Kernel 2: LIF scan, one thread per (b,h) lane, prefetch 4 steps ahead.
// ============================================================================
__global__ void __launch_bounds__(256) scan_kernel(float* __restrict__ out)
{
    const int u = blockIdx.x * blockDim.x + threadIdx.x;   // 0..NBH-1
    const size_t MOFF = (size_t)(TT + 1) * NBH;

    float syn = 0.f, mem = 0.f;
    out[u] = 0.f;
    out[MOFF + u] = 0.f;

    float buf[4], nbuf[4];
#pragma unroll
    for (int j = 0; j < 4; j++) buf[j] = g_proj[(size_t)j * NBH + u];

    for (int g = 0; g < TT / 4; g++) {
        if (g + 1 < TT / 4) {
#pragma unroll
            for (int j = 0; j < 4; j++)
                nbuf[j] = g_proj[(size_t)((g + 1) * 4 + j) * NBH + u];
        }
#pragma unroll
        for (int j = 0; j < 4; j++) {
            int t = g * 4 + j;
            float mthr  = mem - 1.0f;
            float spike = (mthr > 0.0f) ? 1.0f : 0.0f;
            float nsyn  = ALPHA_F * syn + buf[j];
            float nmem  = BETA_F * mem + syn - spike;   // uses OLD syn
            out[(size_t)(t + 1) * NBH + u]        = spike;
            out[MOFF + (size_t)(t + 1) * NBH + u] = nmem;
            syn = nsyn;
            mem = nmem;
        }
#pragma unroll
        for (int j = 0; j < 4; j++) buf[j] = nbuf[j];
    }
}

// ============================================================================
extern "C" void kernel_launch(void* const* d_in, const int* in_sizes, int n_in,
                              void* d_out, int out_size)
{
    const float* x    = (const float*)d_in[0];
    const float* W    = (const float*)d_in[1];
    const float* bias = (const float*)d_in[2];
    float* out = (float*)d_out;

    const int smem_bytes = (2 * XS_ELEMS + HH * WS_STRIDE) * sizeof(float); // 163072
    cudaFuncSetAttribute(proj_kernel,
                         cudaFuncAttributeMaxDynamicSharedMemorySize, smem_bytes);

    proj_kernel<<<MM / RPB, BLK, smem_bytes>>>(x, W, bias);
    scan_kernel<<<NBH / 256, 256>>>(out);
}